// round 1
// baseline (speedup 1.0000x reference)
#include <cuda_runtime.h>
#include <math.h>

#define NBATCH 16

// ---------------- static scratch (allowed: __device__ globals) ----------------
__device__ float g_wT[4*4*20*160*4];      // wide weights  [l][k][ci4][o(160)][4]
__device__ float g_w1T[4*20*80*4];        // 1x1 weights   [l][ci4][o(80)][4]
__device__ float g_f0T[20*80*4];          // head f0       [ci4][o][4]
__device__ float g_f1T[20*80*4];          // head f1       [ci4][o][4]
__device__ float g_embT[80*512];          // embedding^T   [v][code]
__device__ float g_e2[512];
__device__ float g_edot[512*2];
__device__ float g_qdot[NBATCH*512*2];
__device__ unsigned g_maxkey[NBATCH*2];
__device__ float g_bufA[NBATCH*4096*80];
__device__ float g_bufB[NBATCH*4096*80];
__device__ float g_bufC[NBATCH*4096*80];
__device__ float g_encs[NBATCH*2048*80];
__device__ float g_encq[NBATCH*512*80];

__device__ __forceinline__ unsigned fkey(float f) {
    unsigned u = __float_as_uint(f);
    return (u & 0x80000000u) ? ~u : (u | 0x80000000u);
}
__device__ __forceinline__ float funkey(unsigned k) {
    unsigned u = (k & 0x80000000u) ? (k & 0x7FFFFFFFu) : ~k;
    return __uint_as_float(u);
}

// ---------------- prep: weight transposes + embedding tables + init ----------------
__global__ void prep_kernel(const float* __restrict__ w_wide,
                            const float* __restrict__ w_1x1,
                            const float* __restrict__ w_f0,
                            const float* __restrict__ w_f1,
                            const float* __restrict__ emb,
                            const float* __restrict__ w_lin) {
    int i = blockIdx.x * blockDim.x + threadIdx.x;
    // wide: 4*4*20*160*4 = 204800
    if (i < 204800) {
        int cc = i & 3; int j = i >> 2;
        int o = j % 160; j /= 160;
        int ci4 = j % 20; j /= 20;
        int k = j % 4; int l = j >> 2;
        g_wT[i] = w_wide[((l*160 + o)*80 + (ci4*4 + cc))*4 + k];
        return;
    }
    i -= 204800;
    // 1x1: 4*20*80*4 = 25600
    if (i < 25600) {
        int cc = i & 3; int j = i >> 2;
        int o = j % 80; j /= 80;
        int ci4 = j % 20; int l = j / 20;
        g_w1T[i] = w_1x1[(l*80 + o)*80 + (ci4*4 + cc)];
        return;
    }
    i -= 25600;
    if (i < 6400) {
        int cc = i & 3; int j = i >> 2;
        int o = j % 80; int ci4 = j / 80;
        g_f0T[i] = w_f0[o*80 + (ci4*4 + cc)];
        return;
    }
    i -= 6400;
    if (i < 6400) {
        int cc = i & 3; int j = i >> 2;
        int o = j % 80; int ci4 = j / 80;
        g_f1T[i] = w_f1[o*80 + (ci4*4 + cc)];
        return;
    }
    i -= 6400;
    if (i < 80*512) {
        int code = i % 512; int v = i / 512;
        g_embT[i] = emb[code*80 + v];
        return;
    }
    i -= 80*512;
    if (i < 512) {
        float s = 0.f, d0 = 0.f, d1 = 0.f;
        for (int v = 0; v < 80; v++) {
            float e = emb[i*80 + v];
            s += e*e;
            d0 += e * w_lin[v];
            d1 += e * w_lin[80 + v];
        }
        g_e2[i] = s; g_edot[i*2] = d0; g_edot[i*2+1] = d1;
        return;
    }
    i -= 512;
    if (i < NBATCH*2) g_maxkey[i] = 0x007FFFFFu;  // key(-inf)
}

// ---------------- wide conv (k=4) + GLU ----------------
// block (80,2); 16 time-steps per thread => 32 output times per block
__global__ void wide_glu_kernel(const float* __restrict__ xin, float* __restrict__ x2out,
                                const float4* __restrict__ wT4, const float* __restrict__ b,
                                int Tin, int Tout, int stride) {
    __shared__ float4 s4[66*20];  // up to 66 input rows x 20 float4
    int n = blockIdx.y;
    int t0 = blockIdx.x * 32;
    int base_in = t0 * stride;
    int nrows = 31*stride + 4;
    int c = threadIdx.x, tt = threadIdx.y;
    int tid = tt*80 + c;

    const float4* xrow4 = (const float4*)(xin + (size_t)n * Tin * 80);
    for (int idx = tid; idx < nrows*20; idx += 160) {
        int r = idx / 20, q = idx % 20;
        int tg = base_in + r;
        s4[idx] = (tg < Tin) ? xrow4[(size_t)tg*20 + q] : make_float4(0.f,0.f,0.f,0.f);
    }
    __syncthreads();

    float a[16], g[16];
    #pragma unroll
    for (int j = 0; j < 16; j++) { a[j] = 0.f; g[j] = 0.f; }

    for (int k = 0; k < 4; k++) {
        for (int ci4 = 0; ci4 < 20; ci4++) {
            float4 wa = wT4[(k*20 + ci4)*160 + c];
            float4 wg = wT4[(k*20 + ci4)*160 + c + 80];
            #pragma unroll
            for (int j = 0; j < 16; j++) {
                int tl = tt*16 + j;
                float4 xv = s4[(tl*stride + k)*20 + ci4];
                a[j] = fmaf(wa.x, xv.x, fmaf(wa.y, xv.y, fmaf(wa.z, xv.z, fmaf(wa.w, xv.w, a[j]))));
                g[j] = fmaf(wg.x, xv.x, fmaf(wg.y, xv.y, fmaf(wg.z, xv.z, fmaf(wg.w, xv.w, g[j]))));
            }
        }
    }

    float ba = b[c], bg = b[c + 80];
    float* orow = x2out + (size_t)n * Tout * 80;
    #pragma unroll
    for (int j = 0; j < 16; j++) {
        int t = t0 + tt*16 + j;
        if (t < Tout) {
            float A = a[j] + ba, G = g[j] + bg;
            float val = tanhf(A) * (1.f / (1.f + __expf(-G)));
            orow[(size_t)t*80 + c] = val;
        }
    }
}

// ---------------- 1x1 conv + optional residual ----------------
// block (80,2); 8 time-steps per thread => 16 times per block
__global__ void conv1x1_res_kernel(const float* __restrict__ x2, const float* __restrict__ res,
                                   float* __restrict__ out, const float4* __restrict__ w4,
                                   const float* __restrict__ b,
                                   int Tout, int Tres, int resOff, int stride) {
    __shared__ float4 s4[16*20];
    int n = blockIdx.y;
    int t0 = blockIdx.x * 16;
    int c = threadIdx.x, tt = threadIdx.y;
    int tid = tt*80 + c;

    const float4* xr = (const float4*)(x2 + (size_t)n * Tout * 80);
    for (int idx = tid; idx < 16*20; idx += 160) {
        int r = idx / 20, q = idx % 20;
        int t = t0 + r;
        s4[idx] = (t < Tout) ? xr[(size_t)t*20 + q] : make_float4(0.f,0.f,0.f,0.f);
    }
    __syncthreads();

    float acc[8];
    #pragma unroll
    for (int j = 0; j < 8; j++) acc[j] = 0.f;

    for (int ci4 = 0; ci4 < 20; ci4++) {
        float4 w = w4[ci4*80 + c];
        #pragma unroll
        for (int j = 0; j < 8; j++) {
            float4 xv = s4[(tt*8 + j)*20 + ci4];
            acc[j] = fmaf(w.x, xv.x, fmaf(w.y, xv.y, fmaf(w.z, xv.z, fmaf(w.w, xv.w, acc[j]))));
        }
    }

    float bc = b[c];
    float* orow = out + (size_t)n * Tout * 80;
    const float* rrow = res ? (res + (size_t)n * Tres * 80) : nullptr;
    #pragma unroll
    for (int j = 0; j < 8; j++) {
        int t = t0 + tt*8 + j;
        if (t < Tout) {
            float v = acc[j] + bc;
            if (rrow) v += rrow[(size_t)(resOff + t*stride)*80 + c];
            orow[(size_t)t*80 + c] = v;
        }
    }
}

// ---------------- fused head: relu(f0 x) -> f1 ----------------
// block (80,8): 8 times per block
__global__ void head_kernel(const float* __restrict__ x, float* __restrict__ enc,
                            const float4* __restrict__ f0, const float4* __restrict__ f1,
                            const float* __restrict__ b0, const float* __restrict__ b1, int T) {
    __shared__ float4 xs[8*20];
    __shared__ __align__(16) float hs[8*80];
    int n = blockIdx.y;
    int t0 = blockIdx.x * 8;
    int c = threadIdx.x, tt = threadIdx.y;
    int tid = tt*80 + c;

    const float4* xr = (const float4*)(x + (size_t)n * T * 80);
    for (int idx = tid; idx < 8*20; idx += 640) {
        int r = idx / 20, q = idx % 20;
        int t = t0 + r;
        xs[idx] = (t < T) ? xr[(size_t)t*20 + q] : make_float4(0.f,0.f,0.f,0.f);
    }
    __syncthreads();

    float acc = b0[c];
    for (int ci4 = 0; ci4 < 20; ci4++) {
        float4 w = f0[ci4*80 + c];
        float4 xv = xs[tt*20 + ci4];
        acc = fmaf(w.x, xv.x, fmaf(w.y, xv.y, fmaf(w.z, xv.z, fmaf(w.w, xv.w, acc))));
    }
    hs[tt*80 + c] = fmaxf(acc, 0.f);
    __syncthreads();

    float o = b1[c];
    const float4* hv4 = (const float4*)hs;
    for (int ci4 = 0; ci4 < 20; ci4++) {
        float4 w = f1[ci4*80 + c];
        float4 hv = hv4[tt*20 + ci4];
        o = fmaf(w.x, hv.x, fmaf(w.y, hv.y, fmaf(w.z, hv.z, fmaf(w.w, hv.w, o))));
    }
    int t = t0 + tt;
    if (t < T) enc[((size_t)n*T + t)*80 + c] = o;
}

// ---------------- qdot: enc_q rows dotted with w_lin ----------------
__global__ void qdot_kernel(const float* __restrict__ encq, const float* __restrict__ w_lin, int Tq) {
    int i = blockIdx.x * blockDim.x + threadIdx.x;
    if (i >= NBATCH * Tq * 2) return;
    int cch = i & 1; int row = i >> 1;
    float s = 0.f;
    const float* xr = encq + (size_t)row * 80;
    const float* wr = w_lin + cch * 80;
    for (int v = 0; v < 80; v++) s += xr[v] * wr[v];
    g_qdot[i] = s;
}

// ---------------- VQ argmin + fused linear + max reduce ----------------
// 8 rows per block, 128 threads (each owns 4 codes)
__global__ void vq_kernel(const float* __restrict__ enc, const float* __restrict__ b_lin,
                          int Ts, int Tq, int Tfill, int totalRows) {
    __shared__ __align__(16) float xsT[80][8];
    __shared__ float sx2[8];
    __shared__ float rd[8][128];
    __shared__ int   ri[8][128];
    int tid = threadIdx.x;
    int rowBase = blockIdx.x * 8;

    for (int idx = tid; idx < 640; idx += 128) {
        int v = idx >> 3, r = idx & 7;
        int row = rowBase + r;
        xsT[v][r] = (row < totalRows) ? enc[(size_t)row*80 + v] : 0.f;
    }
    __syncthreads();
    if (tid < 8) {
        float s = 0.f;
        for (int v = 0; v < 80; v++) { float x = xsT[v][tid]; s += x*x; }
        sx2[tid] = s;
    }
    __syncthreads();

    float xe[4][8];
    #pragma unroll
    for (int co = 0; co < 4; co++)
        #pragma unroll
        for (int r = 0; r < 8; r++) xe[co][r] = 0.f;

    for (int v = 0; v < 80; v++) {
        float4 xa = *(const float4*)&xsT[v][0];
        float4 xb = *(const float4*)&xsT[v][4];
        float xr[8] = {xa.x, xa.y, xa.z, xa.w, xb.x, xb.y, xb.z, xb.w};
        #pragma unroll
        for (int co = 0; co < 4; co++) {
            float ev = g_embT[v*512 + co*128 + tid];
            #pragma unroll
            for (int r = 0; r < 8; r++) xe[co][r] = fmaf(xr[r], ev, xe[co][r]);
        }
    }

    float bestd[8]; int besti[8];
    #pragma unroll
    for (int r = 0; r < 8; r++) { bestd[r] = 3.4e38f; besti[r] = 0; }
    #pragma unroll
    for (int co = 0; co < 4; co++) {
        int code = co*128 + tid;
        float e2c = g_e2[code];
        #pragma unroll
        for (int r = 0; r < 8; r++) {
            float d = sx2[r] - 2.f*xe[co][r] + e2c;
            if (d < bestd[r]) { bestd[r] = d; besti[r] = code; }
        }
    }
    #pragma unroll
    for (int r = 0; r < 8; r++) { rd[r][tid] = bestd[r]; ri[r][tid] = besti[r]; }
    __syncthreads();

    for (int s = 64; s > 0; s >>= 1) {
        if (tid < s) {
            #pragma unroll
            for (int r = 0; r < 8; r++) {
                float d2 = rd[r][tid+s]; int i2 = ri[r][tid+s];
                float d1 = rd[r][tid];   int i1 = ri[r][tid];
                if (d2 < d1 || (d2 == d1 && i2 < i1)) { rd[r][tid] = d2; ri[r][tid] = i2; }
            }
        }
        __syncthreads();
    }

    if (tid < 8) {
        int row = rowBase + tid;
        if (row < totalRows) {
            int n = row / Ts;
            int t = row % Ts;
            int idx = ri[tid][0];
            float q0 = 0.f, q1 = 0.f;
            if (t < Tfill) {
                int tq = t % Tq;
                q0 = g_qdot[((size_t)n*Tq + tq)*2];
                q1 = g_qdot[((size_t)n*Tq + tq)*2 + 1];
            }
            float s0 = q0 + g_edot[idx*2]     + b_lin[0];
            float s1 = q1 + g_edot[idx*2 + 1] + b_lin[1];
            atomicMax(&g_maxkey[n*2],     fkey(s0));
            atomicMax(&g_maxkey[n*2 + 1], fkey(s1));
        }
    }
}

__global__ void final_kernel(float* __restrict__ out) {
    int i = threadIdx.x;
    if (i < NBATCH*2) out[i] = tanhf(funkey(g_maxkey[i]));
}

// ---------------- host orchestration ----------------
static int run_encoder(const float* input, int T0,
                       float* pX, float* pX2, float* pY, float* encout,
                       const float* wT, const float* b_wide,
                       const float* w1T, const float* b_1x1,
                       const float* f0T, const float* b_f0,
                       const float* f1T, const float* b_f1) {
    int T = T0;
    const float* cur = input;
    float* bufs[2] = { pX, pY };
    int flip = 0;
    for (int l = 0; l < 4; l++) {
        int stride = (l < 2) ? 2 : 1;
        int Tout = (T - 4) / stride + 1;
        dim3 gw((Tout + 31) / 32, NBATCH), bw(80, 2);
        wide_glu_kernel<<<gw, bw>>>(cur, pX2,
            (const float4*)(wT + (size_t)l * 4*20*160*4), b_wide + l*160, T, Tout, stride);
        float* nxt = bufs[flip];
        dim3 g1((Tout + 15) / 16, NBATCH), b1(80, 2);
        conv1x1_res_kernel<<<g1, b1>>>(pX2, (l == 0) ? nullptr : cur, nxt,
            (const float4*)(w1T + (size_t)l * 20*80*4), b_1x1 + l*80,
            Tout, T, 3, stride);
        cur = nxt; flip ^= 1; T = Tout;
    }
    dim3 gh((T + 7) / 8, NBATCH), bh(80, 8);
    head_kernel<<<gh, bh>>>(cur, encout, (const float4*)f0T, (const float4*)f1T, b_f0, b_f1, T);
    return T;
}

extern "C" void kernel_launch(void* const* d_in, const int* in_sizes, int n_in,
                              void* d_out, int out_size) {
    const float* search = (const float*)d_in[0];
    const float* query  = (const float*)d_in[1];
    const float* w_wide = (const float*)d_in[2];
    const float* b_wide = (const float*)d_in[3];
    const float* w_1x1  = (const float*)d_in[4];
    const float* b_1x1  = (const float*)d_in[5];
    const float* w_f0   = (const float*)d_in[6];
    const float* b_f0   = (const float*)d_in[7];
    const float* w_f1   = (const float*)d_in[8];
    const float* b_f1   = (const float*)d_in[9];
    const float* emb    = (const float*)d_in[10];
    const float* w_lin  = (const float*)d_in[11];
    const float* b_lin  = (const float*)d_in[12];

    int Ts = in_sizes[0] / (NBATCH * 80);
    int Tq = in_sizes[1] / (NBATCH * 80);

    float *pA, *pB, *pC, *pEncS, *pEncQ, *pWT, *pW1T, *pF0T, *pF1T;
    cudaGetSymbolAddress((void**)&pA, g_bufA);
    cudaGetSymbolAddress((void**)&pB, g_bufB);
    cudaGetSymbolAddress((void**)&pC, g_bufC);
    cudaGetSymbolAddress((void**)&pEncS, g_encs);
    cudaGetSymbolAddress((void**)&pEncQ, g_encq);
    cudaGetSymbolAddress((void**)&pWT, g_wT);
    cudaGetSymbolAddress((void**)&pW1T, g_w1T);
    cudaGetSymbolAddress((void**)&pF0T, g_f0T);
    cudaGetSymbolAddress((void**)&pF1T, g_f1T);

    int prepTotal = 204800 + 25600 + 6400 + 6400 + 80*512 + 512 + NBATCH*2;
    prep_kernel<<<(prepTotal + 255) / 256, 256>>>(w_wide, w_1x1, w_f0, w_f1, emb, w_lin);

    int Ts4 = run_encoder(search, Ts, pA, pB, pC, pEncS,
                          pWT, b_wide, pW1T, b_1x1, pF0T, b_f0, pF1T, b_f1);
    int Tq4 = run_encoder(query, Tq, pA, pB, pC, pEncQ,
                          pWT, b_wide, pW1T, b_1x1, pF0T, b_f0, pF1T, b_f1);

    qdot_kernel<<<(NBATCH*Tq4*2 + 255) / 256, 256>>>(pEncQ, w_lin, Tq4);

    int sf = Ts4 / Tq4;
    int Tfill = sf * Tq4;
    int totalRows = NBATCH * Ts4;
    vq_kernel<<<(totalRows + 7) / 8, 128>>>(pEncS, b_lin, Ts4, Tq4, Tfill, totalRows);

    final_kernel<<<1, 32>>>((float*)d_out);
}

// round 3
// speedup vs baseline: 1.1689x; 1.1689x over previous
#include <cuda_runtime.h>
#include <math.h>

#define NBATCH 16

// ---------------- static scratch ----------------
__device__ float g_wT[4*4*20*160*4];      // wide weights  [l][k][ci4][o(160)][4]
__device__ float g_w1T[4*20*80*4];        // 1x1 weights   [l][ci4][o(80)][4]
__device__ float g_f0T[20*80*4];          // head f0       [ci4][o][4]
__device__ float g_f1T[20*80*4];          // head f1       [ci4][o][4]
__device__ float g_embT[80*512];          // embedding^T   [v][code]
__device__ float g_e2[512];
__device__ float g_edot[512*2];
__device__ float g_qdot[NBATCH*512*2];
__device__ unsigned g_maxkey[NBATCH*2];
__device__ float g_bufA[NBATCH*4096*80];  // search ping
__device__ float g_bufB[NBATCH*4096*80];  // search pong
__device__ float g_bufC[NBATCH*4096*80];  // query ping (first half) / pong (second half)
__device__ float g_encs[NBATCH*2048*80];
__device__ float g_encq[NBATCH*512*80];

__device__ __forceinline__ unsigned fkey(float f) {
    unsigned u = __float_as_uint(f);
    return (u & 0x80000000u) ? ~u : (u | 0x80000000u);
}
__device__ __forceinline__ float funkey(unsigned k) {
    unsigned u = (k & 0x80000000u) ? (k & 0x7FFFFFFFu) : ~k;
    return __uint_as_float(u);
}

// ---------------- prep: weight transposes + embedding tables + init ----------------
__global__ void prep_kernel(const float* __restrict__ w_wide,
                            const float* __restrict__ w_1x1,
                            const float* __restrict__ w_f0,
                            const float* __restrict__ w_f1,
                            const float* __restrict__ emb,
                            const float* __restrict__ w_lin) {
    int i = blockIdx.x * blockDim.x + threadIdx.x;
    if (i < 204800) {
        int cc = i & 3; int j = i >> 2;
        int o = j % 160; j /= 160;
        int ci4 = j % 20; j /= 20;
        int k = j % 4; int l = j >> 2;
        g_wT[i] = w_wide[((l*160 + o)*80 + (ci4*4 + cc))*4 + k];
        return;
    }
    i -= 204800;
    if (i < 25600) {
        int cc = i & 3; int j = i >> 2;
        int o = j % 80; j /= 80;
        int ci4 = j % 20; int l = j / 20;
        g_w1T[i] = w_1x1[(l*80 + o)*80 + (ci4*4 + cc)];
        return;
    }
    i -= 25600;
    if (i < 6400) {
        int cc = i & 3; int j = i >> 2;
        int o = j % 80; int ci4 = j / 80;
        g_f0T[i] = w_f0[o*80 + (ci4*4 + cc)];
        return;
    }
    i -= 6400;
    if (i < 6400) {
        int cc = i & 3; int j = i >> 2;
        int o = j % 80; int ci4 = j / 80;
        g_f1T[i] = w_f1[o*80 + (ci4*4 + cc)];
        return;
    }
    i -= 6400;
    if (i < 80*512) {
        int code = i % 512; int v = i / 512;
        g_embT[i] = emb[code*80 + v];
        return;
    }
    i -= 80*512;
    if (i < 512) {
        float s = 0.f, d0 = 0.f, d1 = 0.f;
        for (int v = 0; v < 80; v++) {
            float e = emb[i*80 + v];
            s += e*e;
            d0 += e * w_lin[v];
            d1 += e * w_lin[80 + v];
        }
        g_e2[i] = s; g_edot[i*2] = d0; g_edot[i*2+1] = d1;
        return;
    }
    i -= 512;
    if (i < NBATCH*2) g_maxkey[i] = 0x007FFFFFu;  // key(-inf)
}

// ---------------- fused layer: wide conv + GLU + 1x1 (+res) (+head) ----------------
// block (80,2); 32 output times per block; search and query share the grid.
template<bool RES, bool HEAD>
__global__ void layer_kernel(const float* __restrict__ xS, const float* __restrict__ xQ,
                             float* __restrict__ oS, float* __restrict__ oQ,
                             float* __restrict__ encS, float* __restrict__ encQ,
                             const float4* __restrict__ wT4, const float* __restrict__ bw,
                             const float4* __restrict__ w1, const float* __restrict__ b1,
                             const float4* __restrict__ f0, const float4* __restrict__ f1,
                             const float* __restrict__ bf0, const float* __restrict__ bf1,
                             int TinS, int ToutS, int tilesS,
                             int TinQ, int ToutQ, int stride) {
    __shared__ float4 s4[66*20];        // input tile (also residual source)
    __shared__ float  s_glu[32][80];    // GLU outputs (reused as relu-hidden for head)
    __shared__ float  s_out[32][80];    // 1x1+res outputs (head input)

    int n = blockIdx.y;
    bool isQ = ((int)blockIdx.x >= tilesS);
    int tile = isQ ? ((int)blockIdx.x - tilesS) : (int)blockIdx.x;
    const float* xin = isQ ? xQ : xS;
    int Tin  = isQ ? TinQ  : TinS;
    int Tout = isQ ? ToutQ : ToutS;
    float* out = isQ ? oQ : oS;
    float* enc = isQ ? encQ : encS;

    int t0 = tile * 32;
    int base_in = t0 * stride;
    int nrows = 31*stride + 4;
    int c = threadIdx.x, tt = threadIdx.y;
    int tid = tt*80 + c;

    // ---- load input tile ----
    const float4* xrow4 = (const float4*)(xin + (size_t)n * Tin * 80);
    for (int idx = tid; idx < nrows*20; idx += 160) {
        int r = idx / 20, q = idx % 20;
        int tg = base_in + r;
        s4[idx] = (tg < Tin) ? xrow4[(size_t)tg*20 + q] : make_float4(0.f,0.f,0.f,0.f);
    }
    __syncthreads();

    // ---- phase 1: wide conv (160ch) + GLU ----
    float a[16], g[16];
    #pragma unroll
    for (int j = 0; j < 16; j++) { a[j] = 0.f; g[j] = 0.f; }

    for (int k = 0; k < 4; k++) {
        for (int ci4 = 0; ci4 < 20; ci4++) {
            float4 wa = wT4[(k*20 + ci4)*160 + c];
            float4 wg = wT4[(k*20 + ci4)*160 + c + 80];
            #pragma unroll
            for (int j = 0; j < 16; j++) {
                int tl = tt*16 + j;
                float4 xv = s4[(tl*stride + k)*20 + ci4];
                a[j] = fmaf(wa.x, xv.x, fmaf(wa.y, xv.y, fmaf(wa.z, xv.z, fmaf(wa.w, xv.w, a[j]))));
                g[j] = fmaf(wg.x, xv.x, fmaf(wg.y, xv.y, fmaf(wg.z, xv.z, fmaf(wg.w, xv.w, g[j]))));
            }
        }
    }
    {
        float ba = bw[c], bg = bw[c + 80];
        #pragma unroll
        for (int j = 0; j < 16; j++) {
            float A = a[j] + ba, G = g[j] + bg;
            s_glu[tt*16 + j][c] = tanhf(A) * (1.f / (1.f + __expf(-G)));
        }
    }
    __syncthreads();

    // ---- phase 2: 1x1 conv (+ residual from input tile) ----
    float acc[16];
    #pragma unroll
    for (int j = 0; j < 16; j++) acc[j] = 0.f;
    for (int ci4 = 0; ci4 < 20; ci4++) {
        float4 w = w1[ci4*80 + c];
        #pragma unroll
        for (int j = 0; j < 16; j++) {
            float4 xv = *(const float4*)&s_glu[tt*16 + j][ci4*4];
            acc[j] = fmaf(w.x, xv.x, fmaf(w.y, xv.y, fmaf(w.z, xv.z, fmaf(w.w, xv.w, acc[j]))));
        }
    }
    {
        float bc = b1[c];
        const float* s_in_f = (const float*)s4;
        float* orow = out + (size_t)n * Tout * 80;
        #pragma unroll
        for (int j = 0; j < 16; j++) {
            int jl = tt*16 + j;
            int t = t0 + jl;
            float v = acc[j] + bc;
            if (RES) v += s_in_f[(jl*stride + 3)*80 + c];
            if (HEAD) {
                s_out[jl][c] = v;
            } else {
                if (t < Tout) orow[(size_t)t*80 + c] = v;
            }
        }
    }

    if (HEAD) {
        __syncthreads();
        // f0 + relu -> s_glu (reused)
        float h[16];
        #pragma unroll
        for (int j = 0; j < 16; j++) h[j] = 0.f;
        for (int ci4 = 0; ci4 < 20; ci4++) {
            float4 w = f0[ci4*80 + c];
            #pragma unroll
            for (int j = 0; j < 16; j++) {
                float4 xv = *(const float4*)&s_out[tt*16 + j][ci4*4];
                h[j] = fmaf(w.x, xv.x, fmaf(w.y, xv.y, fmaf(w.z, xv.z, fmaf(w.w, xv.w, h[j]))));
            }
        }
        {
            float b0c = bf0[c];
            #pragma unroll
            for (int j = 0; j < 16; j++)
                s_glu[tt*16 + j][c] = fmaxf(h[j] + b0c, 0.f);
        }
        __syncthreads();
        // f1 -> enc
        float o[16];
        #pragma unroll
        for (int j = 0; j < 16; j++) o[j] = 0.f;
        for (int ci4 = 0; ci4 < 20; ci4++) {
            float4 w = f1[ci4*80 + c];
            #pragma unroll
            for (int j = 0; j < 16; j++) {
                float4 xv = *(const float4*)&s_glu[tt*16 + j][ci4*4];
                o[j] = fmaf(w.x, xv.x, fmaf(w.y, xv.y, fmaf(w.z, xv.z, fmaf(w.w, xv.w, o[j]))));
            }
        }
        {
            float b1c = bf1[c];
            #pragma unroll
            for (int j = 0; j < 16; j++) {
                int t = t0 + tt*16 + j;
                if (t < Tout) enc[((size_t)n*Tout + t)*80 + c] = o[j] + b1c;
            }
        }
    }
}

// ---------------- qdot: enc_q rows dotted with w_lin ----------------
__global__ void qdot_kernel(const float* __restrict__ encq, const float* __restrict__ w_lin, int Tq) {
    int i = blockIdx.x * blockDim.x + threadIdx.x;
    if (i >= NBATCH * Tq * 2) return;
    int cch = i & 1; int row = i >> 1;
    float s = 0.f;
    const float* xr = encq + (size_t)row * 80;
    const float* wr = w_lin + cch * 80;
    for (int v = 0; v < 80; v++) s += xr[v] * wr[v];
    g_qdot[i] = s;
}

// ---------------- VQ argmin + fused linear + max reduce ----------------
// 16 rows per block, 128 threads (each owns 4 codes)
__global__ void vq_kernel(const float* __restrict__ enc, const float* __restrict__ b_lin,
                          int Ts, int Tq, int Tfill, int totalRows) {
    __shared__ __align__(16) float xsT[80][16];
    __shared__ float sx2[16];
    __shared__ float rd[16][128];
    __shared__ int   ri[16][128];
    int tid = threadIdx.x;
    int rowBase = blockIdx.x * 16;

    for (int idx = tid; idx < 1280; idx += 128) {
        int v = idx >> 4, r = idx & 15;
        int row = rowBase + r;
        xsT[v][r] = (row < totalRows) ? enc[(size_t)row*80 + v] : 0.f;
    }
    __syncthreads();
    if (tid < 16) {
        float s = 0.f;
        for (int v = 0; v < 80; v++) { float x = xsT[v][tid]; s += x*x; }
        sx2[tid] = s;
    }
    __syncthreads();

    float xe[4][16];
    #pragma unroll
    for (int co = 0; co < 4; co++)
        #pragma unroll
        for (int r = 0; r < 16; r++) xe[co][r] = 0.f;

    #pragma unroll 4
    for (int v = 0; v < 80; v++) {
        float4 xa = *(const float4*)&xsT[v][0];
        float4 xb = *(const float4*)&xsT[v][4];
        float4 xc = *(const float4*)&xsT[v][8];
        float4 xd = *(const float4*)&xsT[v][12];
        float xr[16] = {xa.x, xa.y, xa.z, xa.w, xb.x, xb.y, xb.z, xb.w,
                        xc.x, xc.y, xc.z, xc.w, xd.x, xd.y, xd.z, xd.w};
        #pragma unroll
        for (int co = 0; co < 4; co++) {
            float ev = g_embT[v*512 + co*128 + tid];
            #pragma unroll
            for (int r = 0; r < 16; r++) xe[co][r] = fmaf(xr[r], ev, xe[co][r]);
        }
    }

    float bestd[16]; int besti[16];
    #pragma unroll
    for (int r = 0; r < 16; r++) { bestd[r] = 3.4e38f; besti[r] = 0; }
    #pragma unroll
    for (int co = 0; co < 4; co++) {
        int code = co*128 + tid;
        float e2c = g_e2[code];
        #pragma unroll
        for (int r = 0; r < 16; r++) {
            float d = sx2[r] - 2.f*xe[co][r] + e2c;
            if (d < bestd[r]) { bestd[r] = d; besti[r] = code; }
        }
    }
    #pragma unroll
    for (int r = 0; r < 16; r++) { rd[r][tid] = bestd[r]; ri[r][tid] = besti[r]; }
    __syncthreads();

    for (int s = 64; s > 0; s >>= 1) {
        if (tid < s) {
            #pragma unroll
            for (int r = 0; r < 16; r++) {
                float d2 = rd[r][tid+s]; int i2 = ri[r][tid+s];
                float d1 = rd[r][tid];   int i1 = ri[r][tid];
                if (d2 < d1 || (d2 == d1 && i2 < i1)) { rd[r][tid] = d2; ri[r][tid] = i2; }
            }
        }
        __syncthreads();
    }

    if (tid < 16) {
        int row = rowBase + tid;
        if (row < totalRows) {
            int n = row / Ts;
            int t = row % Ts;
            int idx = ri[tid][0];
            float q0 = 0.f, q1 = 0.f;
            if (t < Tfill) {
                int tq = t % Tq;
                q0 = g_qdot[((size_t)n*Tq + tq)*2];
                q1 = g_qdot[((size_t)n*Tq + tq)*2 + 1];
            }
            float s0 = q0 + g_edot[idx*2]     + b_lin[0];
            float s1 = q1 + g_edot[idx*2 + 1] + b_lin[1];
            atomicMax(&g_maxkey[n*2],     fkey(s0));
            atomicMax(&g_maxkey[n*2 + 1], fkey(s1));
        }
    }
}

__global__ void final_kernel(float* __restrict__ out) {
    int i = threadIdx.x;
    if (i < NBATCH*2) out[i] = tanhf(funkey(g_maxkey[i]));
}

// ---------------- host orchestration ----------------
extern "C" void kernel_launch(void* const* d_in, const int* in_sizes, int n_in,
                              void* d_out, int out_size) {
    const float* search = (const float*)d_in[0];
    const float* query  = (const float*)d_in[1];
    const float* w_wide = (const float*)d_in[2];
    const float* b_wide = (const float*)d_in[3];
    const float* w_1x1  = (const float*)d_in[4];
    const float* b_1x1  = (const float*)d_in[5];
    const float* w_f0   = (const float*)d_in[6];
    const float* b_f0   = (const float*)d_in[7];
    const float* w_f1   = (const float*)d_in[8];
    const float* b_f1   = (const float*)d_in[9];
    const float* emb    = (const float*)d_in[10];
    const float* w_lin  = (const float*)d_in[11];
    const float* b_lin  = (const float*)d_in[12];

    int Ts = in_sizes[0] / (NBATCH * 80);
    int Tq = in_sizes[1] / (NBATCH * 80);

    float *pA, *pB, *pC, *pEncS, *pEncQ, *pWT, *pW1T, *pF0T, *pF1T;
    cudaGetSymbolAddress((void**)&pA, g_bufA);
    cudaGetSymbolAddress((void**)&pB, g_bufB);
    cudaGetSymbolAddress((void**)&pC, g_bufC);
    cudaGetSymbolAddress((void**)&pEncS, g_encs);
    cudaGetSymbolAddress((void**)&pEncQ, g_encq);
    cudaGetSymbolAddress((void**)&pWT, g_wT);
    cudaGetSymbolAddress((void**)&pW1T, g_w1T);
    cudaGetSymbolAddress((void**)&pF0T, g_f0T);
    cudaGetSymbolAddress((void**)&pF1T, g_f1T);

    int prepTotal = 204800 + 25600 + 6400 + 6400 + 80*512 + 512 + NBATCH*2;
    prep_kernel<<<(prepTotal + 255) / 256, 256>>>(w_wide, w_1x1, w_f0, w_f1, emb, w_lin);

    // query ping/pong carved out of g_bufC
    float* qPing = pC;
    float* qPong = pC + (size_t)NBATCH * 2048 * 80;

    const float* curS = search; const float* curQ = query;
    float* sBufs[2] = { pA, pB };
    float* qBufs[2] = { qPing, qPong };
    int TS = Ts, TQ = Tq;
    int flip = 0;
    int ToutS_final = 0, ToutQ_final = 0;

    for (int l = 0; l < 4; l++) {
        int stride = (l < 2) ? 2 : 1;
        int ToutS = (TS - 4) / stride + 1;
        int ToutQ = (TQ - 4) / stride + 1;
        int tilesS = (ToutS + 31) / 32;
        int tilesQ = (ToutQ + 31) / 32;
        dim3 grid(tilesS + tilesQ, NBATCH), block(80, 2);
        float* outS = sBufs[flip];
        float* outQ = qBufs[flip];
        const float4* wT4 = (const float4*)(pWT + (size_t)l * 4*20*160*4);
        const float4* w14 = (const float4*)(pW1T + (size_t)l * 20*80*4);
        if (l == 0) {
            layer_kernel<false,false><<<grid, block>>>(curS, curQ, outS, outQ, pEncS, pEncQ,
                wT4, b_wide + l*160, w14, b_1x1 + l*80,
                (const float4*)pF0T, (const float4*)pF1T, b_f0, b_f1,
                TS, ToutS, tilesS, TQ, ToutQ, stride);
        } else if (l < 3) {
            layer_kernel<true,false><<<grid, block>>>(curS, curQ, outS, outQ, pEncS, pEncQ,
                wT4, b_wide + l*160, w14, b_1x1 + l*80,
                (const float4*)pF0T, (const float4*)pF1T, b_f0, b_f1,
                TS, ToutS, tilesS, TQ, ToutQ, stride);
        } else {
            layer_kernel<true,true><<<grid, block>>>(curS, curQ, outS, outQ, pEncS, pEncQ,
                wT4, b_wide + l*160, w14, b_1x1 + l*80,
                (const float4*)pF0T, (const float4*)pF1T, b_f0, b_f1,
                TS, ToutS, tilesS, TQ, ToutQ, stride);
        }
        curS = outS; curQ = outQ;
        flip ^= 1;
        TS = ToutS; TQ = ToutQ;
        ToutS_final = ToutS; ToutQ_final = ToutQ;
    }

    int Ts4 = ToutS_final, Tq4 = ToutQ_final;

    qdot_kernel<<<(NBATCH*Tq4*2 + 255) / 256, 256>>>(pEncQ, w_lin, Tq4);

    int sf = Ts4 / Tq4;
    int Tfill = sf * Tq4;
    int totalRows = NBATCH * Ts4;
    vq_kernel<<<(totalRows + 15) / 16, 128>>>(pEncS, b_lin, Ts4, Tq4, Tfill, totalRows);

    final_kernel<<<1, 32>>>((float*)d_out);
}

// round 4
// speedup vs baseline: 1.1722x; 1.0028x over previous
#include <cuda_runtime.h>
#include <math.h>

#define NBATCH 16

// ---------------- static scratch ----------------
__device__ float g_wT[4*4*20*160*4];      // wide weights  [l][k][ci4][o(160)][4]
__device__ float g_w1T[4*20*80*4];        // 1x1 weights   [l][ci4][o(80)][4]
__device__ float g_f0T[20*80*4];          // head f0       [ci4][o][4]
__device__ float g_f1T[20*80*4];          // head f1       [ci4][o][4]
__device__ float g_embT[80*512];          // embedding^T   [v][code]
__device__ float g_e2[512];
__device__ float g_edot[512*2];
__device__ float g_qdot[NBATCH*512*2];
__device__ unsigned g_maxkey[NBATCH*2];
__device__ float g_bufA[NBATCH*4096*80];  // search ping
__device__ float g_bufB[NBATCH*4096*80];  // search pong
__device__ float g_bufC[NBATCH*4096*80];  // query ping (first half) / pong (second half)
__device__ float g_encs[NBATCH*2048*80];
__device__ float g_encq[NBATCH*512*80];

__device__ __forceinline__ unsigned fkey(float f) {
    unsigned u = __float_as_uint(f);
    return (u & 0x80000000u) ? ~u : (u | 0x80000000u);
}
__device__ __forceinline__ float funkey(unsigned k) {
    unsigned u = (k & 0x80000000u) ? (k & 0x7FFFFFFFu) : ~k;
    return __uint_as_float(u);
}

// ---------------- prep: weight transposes + embedding tables + init ----------------
__global__ void prep_kernel(const float* __restrict__ w_wide,
                            const float* __restrict__ w_1x1,
                            const float* __restrict__ w_f0,
                            const float* __restrict__ w_f1,
                            const float* __restrict__ emb,
                            const float* __restrict__ w_lin) {
    int i = blockIdx.x * blockDim.x + threadIdx.x;
    if (i < 204800) {
        int cc = i & 3; int j = i >> 2;
        int o = j % 160; j /= 160;
        int ci4 = j % 20; j /= 20;
        int k = j % 4; int l = j >> 2;
        g_wT[i] = w_wide[((l*160 + o)*80 + (ci4*4 + cc))*4 + k];
        return;
    }
    i -= 204800;
    if (i < 25600) {
        int cc = i & 3; int j = i >> 2;
        int o = j % 80; j /= 80;
        int ci4 = j % 20; int l = j / 20;
        g_w1T[i] = w_1x1[(l*80 + o)*80 + (ci4*4 + cc)];
        return;
    }
    i -= 25600;
    if (i < 6400) {
        int cc = i & 3; int j = i >> 2;
        int o = j % 80; int ci4 = j / 80;
        g_f0T[i] = w_f0[o*80 + (ci4*4 + cc)];
        return;
    }
    i -= 6400;
    if (i < 6400) {
        int cc = i & 3; int j = i >> 2;
        int o = j % 80; int ci4 = j / 80;
        g_f1T[i] = w_f1[o*80 + (ci4*4 + cc)];
        return;
    }
    i -= 6400;
    if (i < 80*512) {
        int code = i % 512; int v = i / 512;
        g_embT[i] = emb[code*80 + v];
        return;
    }
    i -= 80*512;
    if (i < 512) {
        float s = 0.f, d0 = 0.f, d1 = 0.f;
        for (int v = 0; v < 80; v++) {
            float e = emb[i*80 + v];
            s += e*e;
            d0 += e * w_lin[v];
            d1 += e * w_lin[80 + v];
        }
        g_e2[i] = s; g_edot[i*2] = d0; g_edot[i*2+1] = d1;
        return;
    }
    i -= 512;
    if (i < NBATCH*2) g_maxkey[i] = 0x007FFFFFu;  // key(-inf)
}

// ---------------- fused layer: wide conv + GLU + 1x1 (+res) (+head) ----------------
// block (80,2); 32 output times per block; search and query share the grid.
template<bool RES, bool HEAD>
__global__ void layer_kernel(const float* __restrict__ xS, const float* __restrict__ xQ,
                             float* __restrict__ oS, float* __restrict__ oQ,
                             float* __restrict__ encS, float* __restrict__ encQ,
                             const float4* __restrict__ wT4, const float* __restrict__ bw,
                             const float4* __restrict__ w1, const float* __restrict__ b1,
                             const float4* __restrict__ f0, const float4* __restrict__ f1,
                             const float* __restrict__ bf0, const float* __restrict__ bf1,
                             int TinS, int ToutS, int tilesS,
                             int TinQ, int ToutQ, int stride) {
    __shared__ float4 s4[66*20];        // input tile (also residual source)
    __shared__ float  s_glu[32][80];    // GLU outputs (reused as relu-hidden for head)
    __shared__ float  s_out[32][80];    // 1x1+res outputs (head input)

    int n = blockIdx.y;
    bool isQ = ((int)blockIdx.x >= tilesS);
    int tile = isQ ? ((int)blockIdx.x - tilesS) : (int)blockIdx.x;
    const float* xin = isQ ? xQ : xS;
    int Tin  = isQ ? TinQ  : TinS;
    int Tout = isQ ? ToutQ : ToutS;
    float* out = isQ ? oQ : oS;
    float* enc = isQ ? encQ : encS;

    int t0 = tile * 32;
    int base_in = t0 * stride;
    int nrows = 31*stride + 4;
    int c = threadIdx.x, tt = threadIdx.y;
    int tid = tt*80 + c;

    // ---- load input tile ----
    const float4* xrow4 = (const float4*)(xin + (size_t)n * Tin * 80);
    for (int idx = tid; idx < nrows*20; idx += 160) {
        int r = idx / 20, q = idx % 20;
        int tg = base_in + r;
        s4[idx] = (tg < Tin) ? xrow4[(size_t)tg*20 + q] : make_float4(0.f,0.f,0.f,0.f);
    }
    __syncthreads();

    // ---- phase 1: wide conv (160ch) + GLU ----
    float a[16], g[16];
    #pragma unroll
    for (int j = 0; j < 16; j++) { a[j] = 0.f; g[j] = 0.f; }

    for (int k = 0; k < 4; k++) {
        for (int ci4 = 0; ci4 < 20; ci4++) {
            float4 wa = wT4[(k*20 + ci4)*160 + c];
            float4 wg = wT4[(k*20 + ci4)*160 + c + 80];
            #pragma unroll
            for (int j = 0; j < 16; j++) {
                int tl = tt*16 + j;
                float4 xv = s4[(tl*stride + k)*20 + ci4];
                a[j] = fmaf(wa.x, xv.x, fmaf(wa.y, xv.y, fmaf(wa.z, xv.z, fmaf(wa.w, xv.w, a[j]))));
                g[j] = fmaf(wg.x, xv.x, fmaf(wg.y, xv.y, fmaf(wg.z, xv.z, fmaf(wg.w, xv.w, g[j]))));
            }
        }
    }
    {
        float ba = bw[c], bg = bw[c + 80];
        #pragma unroll
        for (int j = 0; j < 16; j++) {
            float A = a[j] + ba, G = g[j] + bg;
            s_glu[tt*16 + j][c] = tanhf(A) * (1.f / (1.f + __expf(-G)));
        }
    }
    __syncthreads();

    // ---- phase 2: 1x1 conv (+ residual from input tile) ----
    float acc[16];
    #pragma unroll
    for (int j = 0; j < 16; j++) acc[j] = 0.f;
    for (int ci4 = 0; ci4 < 20; ci4++) {
        float4 w = w1[ci4*80 + c];
        #pragma unroll
        for (int j = 0; j < 16; j++) {
            float4 xv = *(const float4*)&s_glu[tt*16 + j][ci4*4];
            acc[j] = fmaf(w.x, xv.x, fmaf(w.y, xv.y, fmaf(w.z, xv.z, fmaf(w.w, xv.w, acc[j]))));
        }
    }
    {
        float bc = b1[c];
        const float* s_in_f = (const float*)s4;
        float* orow = out + (size_t)n * Tout * 80;
        #pragma unroll
        for (int j = 0; j < 16; j++) {
            int jl = tt*16 + j;
            int t = t0 + jl;
            float v = acc[j] + bc;
            if (RES) v += s_in_f[(jl*stride + 3)*80 + c];
            if (HEAD) {
                s_out[jl][c] = v;
            } else {
                if (t < Tout) orow[(size_t)t*80 + c] = v;
            }
        }
    }

    if (HEAD) {
        __syncthreads();
        // f0 + relu -> s_glu (reused)
        float h[16];
        #pragma unroll
        for (int j = 0; j < 16; j++) h[j] = 0.f;
        for (int ci4 = 0; ci4 < 20; ci4++) {
            float4 w = f0[ci4*80 + c];
            #pragma unroll
            for (int j = 0; j < 16; j++) {
                float4 xv = *(const float4*)&s_out[tt*16 + j][ci4*4];
                h[j] = fmaf(w.x, xv.x, fmaf(w.y, xv.y, fmaf(w.z, xv.z, fmaf(w.w, xv.w, h[j]))));
            }
        }
        {
            float b0c = bf0[c];
            #pragma unroll
            for (int j = 0; j < 16; j++)
                s_glu[tt*16 + j][c] = fmaxf(h[j] + b0c, 0.f);
        }
        __syncthreads();
        // f1 -> enc
        float o[16];
        #pragma unroll
        for (int j = 0; j < 16; j++) o[j] = 0.f;
        for (int ci4 = 0; ci4 < 20; ci4++) {
            float4 w = f1[ci4*80 + c];
            #pragma unroll
            for (int j = 0; j < 16; j++) {
                float4 xv = *(const float4*)&s_glu[tt*16 + j][ci4*4];
                o[j] = fmaf(w.x, xv.x, fmaf(w.y, xv.y, fmaf(w.z, xv.z, fmaf(w.w, xv.w, o[j]))));
            }
        }
        {
            float b1c = bf1[c];
            #pragma unroll
            for (int j = 0; j < 16; j++) {
                int t = t0 + tt*16 + j;
                if (t < Tout) enc[((size_t)n*Tout + t)*80 + c] = o[j] + b1c;
            }
        }
    }
}

// ---------------- qdot: enc_q rows dotted with w_lin ----------------
__global__ void qdot_kernel(const float* __restrict__ encq, const float* __restrict__ w_lin, int Tq) {
    int i = blockIdx.x * blockDim.x + threadIdx.x;
    if (i >= NBATCH * Tq * 2) return;
    int cch = i & 1; int row = i >> 1;
    float s = 0.f;
    const float* xr = encq + (size_t)row * 80;
    const float* wr = w_lin + cch * 80;
    for (int v = 0; v < 80; v++) s += xr[v] * wr[v];
    g_qdot[i] = s;
}

// ---------------- VQ argmin + fused linear + max reduce ----------------
// 16 rows per block, 128 threads (each owns 4 codes)
__global__ void vq_kernel(const float* __restrict__ enc, const float* __restrict__ b_lin,
                          int Ts, int Tq, int Tfill, int totalRows) {
    __shared__ __align__(16) float xsT[80][16];
    __shared__ float sx2[16];
    __shared__ float rd[16][128];
    __shared__ int   ri[16][128];
    int tid = threadIdx.x;
    int rowBase = blockIdx.x * 16;

    for (int idx = tid; idx < 1280; idx += 128) {
        int v = idx >> 4, r = idx & 15;
        int row = rowBase + r;
        xsT[v][r] = (row < totalRows) ? enc[(size_t)row*80 + v] : 0.f;
    }
    __syncthreads();
    if (tid < 16) {
        float s = 0.f;
        for (int v = 0; v < 80; v++) { float x = xsT[v][tid]; s += x*x; }
        sx2[tid] = s;
    }
    __syncthreads();

    float xe[4][16];
    #pragma unroll
    for (int co = 0; co < 4; co++)
        #pragma unroll
        for (int r = 0; r < 16; r++) xe[co][r] = 0.f;

    #pragma unroll 4
    for (int v = 0; v < 80; v++) {
        float4 xa = *(const float4*)&xsT[v][0];
        float4 xb = *(const float4*)&xsT[v][4];
        float4 xc = *(const float4*)&xsT[v][8];
        float4 xd = *(const float4*)&xsT[v][12];
        float xr[16] = {xa.x, xa.y, xa.z, xa.w, xb.x, xb.y, xb.z, xb.w,
                        xc.x, xc.y, xc.z, xc.w, xd.x, xd.y, xd.z, xd.w};
        #pragma unroll
        for (int co = 0; co < 4; co++) {
            float ev = g_embT[v*512 + co*128 + tid];
            #pragma unroll
            for (int r = 0; r < 16; r++) xe[co][r] = fmaf(xr[r], ev, xe[co][r]);
        }
    }

    float bestd[16]; int besti[16];
    #pragma unroll
    for (int r = 0; r < 16; r++) { bestd[r] = 3.4e38f; besti[r] = 0; }
    #pragma unroll
    for (int co = 0; co < 4; co++) {
        int code = co*128 + tid;
        float e2c = g_e2[code];
        #pragma unroll
        for (int r = 0; r < 16; r++) {
            float d = sx2[r] - 2.f*xe[co][r] + e2c;
            if (d < bestd[r]) { bestd[r] = d; besti[r] = code; }
        }
    }
    #pragma unroll
    for (int r = 0; r < 16; r++) { rd[r][tid] = bestd[r]; ri[r][tid] = besti[r]; }
    __syncthreads();

    for (int s = 64; s > 0; s >>= 1) {
        if (tid < s) {
            #pragma unroll
            for (int r = 0; r < 16; r++) {
                float d2 = rd[r][tid+s]; int i2 = ri[r][tid+s];
                float d1 = rd[r][tid];   int i1 = ri[r][tid];
                if (d2 < d1 || (d2 == d1 && i2 < i1)) { rd[r][tid] = d2; ri[r][tid] = i2; }
            }
        }
        __syncthreads();
    }

    if (tid < 16) {
        int row = rowBase + tid;
        if (row < totalRows) {
            int n = row / Ts;
            int t = row % Ts;
            int idx = ri[tid][0];
            float q0 = 0.f, q1 = 0.f;
            if (t < Tfill) {
                int tq = t % Tq;
                q0 = g_qdot[((size_t)n*Tq + tq)*2];
                q1 = g_qdot[((size_t)n*Tq + tq)*2 + 1];
            }
            float s0 = q0 + g_edot[idx*2]     + b_lin[0];
            float s1 = q1 + g_edot[idx*2 + 1] + b_lin[1];
            atomicMax(&g_maxkey[n*2],     fkey(s0));
            atomicMax(&g_maxkey[n*2 + 1], fkey(s1));
        }
    }
}

__global__ void final_kernel(float* __restrict__ out) {
    int i = threadIdx.x;
    if (i < NBATCH*2) out[i] = tanhf(funkey(g_maxkey[i]));
}

// ---------------- host orchestration ----------------
extern "C" void kernel_launch(void* const* d_in, const int* in_sizes, int n_in,
                              void* d_out, int out_size) {
    const float* search = (const float*)d_in[0];
    const float* query  = (const float*)d_in[1];
    const float* w_wide = (const float*)d_in[2];
    const float* b_wide = (const float*)d_in[3];
    const float* w_1x1  = (const float*)d_in[4];
    const float* b_1x1  = (const float*)d_in[5];
    const float* w_f0   = (const float*)d_in[6];
    const float* b_f0   = (const float*)d_in[7];
    const float* w_f1   = (const float*)d_in[8];
    const float* b_f1   = (const float*)d_in[9];
    const float* emb    = (const float*)d_in[10];
    const float* w_lin  = (const float*)d_in[11];
    const float* b_lin  = (const float*)d_in[12];

    int Ts = in_sizes[0] / (NBATCH * 80);
    int Tq = in_sizes[1] / (NBATCH * 80);

    float *pA, *pB, *pC, *pEncS, *pEncQ, *pWT, *pW1T, *pF0T, *pF1T;
    cudaGetSymbolAddress((void**)&pA, g_bufA);
    cudaGetSymbolAddress((void**)&pB, g_bufB);
    cudaGetSymbolAddress((void**)&pC, g_bufC);
    cudaGetSymbolAddress((void**)&pEncS, g_encs);
    cudaGetSymbolAddress((void**)&pEncQ, g_encq);
    cudaGetSymbolAddress((void**)&pWT, g_wT);
    cudaGetSymbolAddress((void**)&pW1T, g_w1T);
    cudaGetSymbolAddress((void**)&pF0T, g_f0T);
    cudaGetSymbolAddress((void**)&pF1T, g_f1T);

    int prepTotal = 204800 + 25600 + 6400 + 6400 + 80*512 + 512 + NBATCH*2;
    prep_kernel<<<(prepTotal + 255) / 256, 256>>>(w_wide, w_1x1, w_f0, w_f1, emb, w_lin);

    // query ping/pong carved out of g_bufC
    float* qPing = pC;
    float* qPong = pC + (size_t)NBATCH * 2048 * 80;

    const float* curS = search; const float* curQ = query;
    float* sBufs[2] = { pA, pB };
    float* qBufs[2] = { qPing, qPong };
    int TS = Ts, TQ = Tq;
    int flip = 0;
    int ToutS_final = 0, ToutQ_final = 0;

    for (int l = 0; l < 4; l++) {
        int stride = (l < 2) ? 2 : 1;
        int ToutS = (TS - 4) / stride + 1;
        int ToutQ = (TQ - 4) / stride + 1;
        int tilesS = (ToutS + 31) / 32;
        int tilesQ = (ToutQ + 31) / 32;
        dim3 grid(tilesS + tilesQ, NBATCH), block(80, 2);
        float* outS = sBufs[flip];
        float* outQ = qBufs[flip];
        const float4* wT4 = (const float4*)(pWT + (size_t)l * 4*20*160*4);
        const float4* w14 = (const float4*)(pW1T + (size_t)l * 20*80*4);
        if (l == 0) {
            layer_kernel<false,false><<<grid, block>>>(curS, curQ, outS, outQ, pEncS, pEncQ,
                wT4, b_wide + l*160, w14, b_1x1 + l*80,
                (const float4*)pF0T, (const float4*)pF1T, b_f0, b_f1,
                TS, ToutS, tilesS, TQ, ToutQ, stride);
        } else if (l < 3) {
            layer_kernel<true,false><<<grid, block>>>(curS, curQ, outS, outQ, pEncS, pEncQ,
                wT4, b_wide + l*160, w14, b_1x1 + l*80,
                (const float4*)pF0T, (const float4*)pF1T, b_f0, b_f1,
                TS, ToutS, tilesS, TQ, ToutQ, stride);
        } else {
            layer_kernel<true,true><<<grid, block>>>(curS, curQ, outS, outQ, pEncS, pEncQ,
                wT4, b_wide + l*160, w14, b_1x1 + l*80,
                (const float4*)pF0T, (const float4*)pF1T, b_f0, b_f1,
                TS, ToutS, tilesS, TQ, ToutQ, stride);
        }
        curS = outS; curQ = outQ;
        flip ^= 1;
        TS = ToutS; TQ = ToutQ;
        ToutS_final = ToutS; ToutQ_final = ToutQ;
    }

    int Ts4 = ToutS_final, Tq4 = ToutQ_final;

    qdot_kernel<<<(NBATCH*Tq4*2 + 255) / 256, 256>>>(pEncQ, w_lin, Tq4);

    int sf = Ts4 / Tq4;
    int Tfill = sf * Tq4;
    int totalRows = NBATCH * Ts4;
    vq_kernel<<<(totalRows + 15) / 16, 128>>>(pEncS, b_lin, Ts4, Tq4, Tfill, totalRows);

    final_kernel<<<1, 32>>>((float*)d_out);
}